// round 9
// baseline (speedup 1.0000x reference)
#include <cuda_runtime.h>
#include <cuda_fp16.h>
#include <cstdint>

#define D_DIM 1024
#define M_DIM 1024
#define N_MAX 16384

#define BM 128
#define BN 256
#define BK 64                       // halves per k-tile = 128 bytes/row
#define STAGES 3
#define NPASS 3
#define TOT_TILES (NPASS * (D_DIM / BK))    // 48

#define STAGE_BYTES (BM * 128 + BN * 128)   // 48 KB (A then B)
#define SMEM_DYN_BYTES (STAGES * STAGE_BYTES)   // 144 KB -> 1 CTA/SM

// ---------------- static device scratch (no allocation allowed) -------------
__device__ __align__(16) float  g_p2[M_DIM];
__device__ __align__(16) __half g_qhi[(size_t)N_MAX * D_DIM];
__device__ __align__(16) __half g_qlo[(size_t)N_MAX * D_DIM];
__device__ __align__(16) __half g_phi[(size_t)M_DIM * D_DIM];
__device__ __align__(16) __half g_plo[(size_t)M_DIM * D_DIM];

// ---------------- helpers ----------------------------------------------------
__device__ __forceinline__ uint32_t smem_to_u32(const void* p) {
    uint32_t a;
    asm("{ .reg .u64 t; cvta.to.shared.u64 t, %1; cvt.u32.u64 %0, t; }" : "=r"(a) : "l"(p));
    return a;
}

__device__ __forceinline__ void cp_async16(uint32_t dst, const void* src) {
    asm volatile("cp.async.cg.shared.global [%0], [%1], 16;" :: "r"(dst), "l"(src) : "memory");
}
#define CP_COMMIT() asm volatile("cp.async.commit_group;" ::: "memory")
#define CP_WAIT(n)  asm volatile("cp.async.wait_group %0;" :: "n"(n) : "memory")

__device__ __forceinline__ void ldsm_x4(uint32_t* r, uint32_t addr) {
    asm volatile("ldmatrix.sync.aligned.m8n8.x4.shared.b16 {%0,%1,%2,%3}, [%4];"
                 : "=r"(r[0]), "=r"(r[1]), "=r"(r[2]), "=r"(r[3]) : "r"(addr));
}

__device__ __forceinline__ void mma16816(float* c, const uint32_t* a, const uint32_t* b) {
    asm volatile(
        "mma.sync.aligned.m16n8k16.row.col.f32.f16.f16.f32 "
        "{%0,%1,%2,%3}, {%4,%5,%6,%7}, {%8,%9}, {%0,%1,%2,%3};"
        : "+f"(c[0]), "+f"(c[1]), "+f"(c[2]), "+f"(c[3])
        : "r"(a[0]), "r"(a[1]), "r"(a[2]), "r"(a[3]), "r"(b[0]), "r"(b[1]));
}

// ---------------------------------------------------------------------------
// Kernel A: split fp32 -> (hi, lo) fp16 pairs for Q and P; fused p2 for P.
// ---------------------------------------------------------------------------
__global__ __launch_bounds__(256) void convert_kernel(const float* __restrict__ q,
                                                      const float* __restrict__ p, int nq) {
    const int row  = blockIdx.x * 8 + (threadIdx.x >> 5);
    const int lane = threadIdx.x & 31;
    const bool isQ = row < nq;
    const float* src = isQ ? (q + (size_t)row * D_DIM) : (p + (size_t)(row - nq) * D_DIM);
    __half* dhi = isQ ? (g_qhi + (size_t)row * D_DIM) : (g_phi + (size_t)(row - nq) * D_DIM);
    __half* dlo = isQ ? (g_qlo + (size_t)row * D_DIM) : (g_plo + (size_t)(row - nq) * D_DIM);

    float4 v[8];
    #pragma unroll
    for (int j = 0; j < 8; j++)
        v[j] = reinterpret_cast<const float4*>(src)[lane + 32 * j];

    #pragma unroll
    for (int j = 0; j < 8; j++) {
        __half h0 = __float2half_rn(v[j].x), h1 = __float2half_rn(v[j].y);
        __half h2 = __float2half_rn(v[j].z), h3 = __float2half_rn(v[j].w);
        __half l0 = __float2half_rn(v[j].x - __half2float(h0));
        __half l1 = __float2half_rn(v[j].y - __half2float(h1));
        __half l2 = __float2half_rn(v[j].z - __half2float(h2));
        __half l3 = __float2half_rn(v[j].w - __half2float(h3));
        __half2 hv[2] = {__halves2half2(h0, h1), __halves2half2(h2, h3)};
        __half2 lv[2] = {__halves2half2(l0, l1), __halves2half2(l2, l3)};
        reinterpret_cast<uint2*>(dhi)[lane + 32 * j] = *reinterpret_cast<uint2*>(hv);
        reinterpret_cast<uint2*>(dlo)[lane + 32 * j] = *reinterpret_cast<uint2*>(lv);
    }

    if (!isQ) {                                 // fused p2 (exact fp32)
        float s = 0.0f;
        #pragma unroll
        for (int j = 0; j < 8; j++)
            s += v[j].x * v[j].x + v[j].y * v[j].y + v[j].z * v[j].z + v[j].w * v[j].w;
        #pragma unroll
        for (int o = 16; o; o >>= 1) s += __shfl_xor_sync(0xffffffffu, s, o);
        if (lane == 0) g_p2[row - nq] = s;
    }
}

// ---------------------------------------------------------------------------
// Kernel B: HMMA GEMM, 128x256 CTA tile, 8 warps (64x64 warp tile), 1 CTA/SM.
// qp = Qhi*Phi^T + Qhi*Plo^T + Qlo*Phi^T -> out
// BK=64, 3-stage cp.async pipeline, one barrier per k-tile.
// ---------------------------------------------------------------------------
struct LoadSlots { uint32_t a_dst[4]; int a_src[4]; uint32_t b_dst[8]; int b_src[8]; };

__device__ __forceinline__ void load_tile(int t, uint32_t smem0,
                                          const __half* const* passA,
                                          const __half* const* passB,
                                          const LoadSlots& ls) {
    const int stage = t % STAGES;
    const __half* A = passA[t >> 4] + (t & 15) * BK;
    const __half* B = passB[t >> 4] + (t & 15) * BK;
    const uint32_t sa = smem0 + stage * STAGE_BYTES;
    const uint32_t sb = sa + BM * 128;
    #pragma unroll
    for (int i = 0; i < 4; i++) cp_async16(sa + ls.a_dst[i], A + ls.a_src[i]);
    #pragma unroll
    for (int i = 0; i < 8; i++) cp_async16(sb + ls.b_dst[i], B + ls.b_src[i]);
}

__global__ __launch_bounds__(256, 1) void gemm_kernel(float* __restrict__ out) {
    extern __shared__ __align__(128) char dsm[];
    const int tid  = threadIdx.x;
    const int lane = tid & 31;
    const int wid  = tid >> 5;
    const int wm   = wid & 1;       // 2 warps along M (64 rows each)
    const int wn   = wid >> 1;      // 4 warps along N (64 cols each)
    const int brow = blockIdx.y * BM;
    const int bcol = blockIdx.x * BN;

    const uint32_t smem0 = smem_to_u32(dsm);

    LoadSlots ls;
    #pragma unroll
    for (int i = 0; i < 4; i++) {               // A: 128 rows x 8 chunks = 1024 slots
        int idx = i * 256 + tid, r = idx >> 3, c = idx & 7;
        uint32_t off = (uint32_t)(r * 128 + c * 16);
        ls.a_dst[i] = off ^ ((off >> 3) & 0x70);
        ls.a_src[i] = r * D_DIM + c * 8;
    }
    #pragma unroll
    for (int i = 0; i < 8; i++) {               // B: 256 rows x 8 chunks = 2048 slots
        int idx = i * 256 + tid, r = idx >> 3, c = idx & 7;
        uint32_t off = (uint32_t)(r * 128 + c * 16);
        ls.b_dst[i] = off ^ ((off >> 3) & 0x70);
        ls.b_src[i] = r * D_DIM + c * 8;
    }

    const __half* passA[NPASS] = {g_qhi + (size_t)brow * D_DIM,
                                  g_qhi + (size_t)brow * D_DIM,
                                  g_qlo + (size_t)brow * D_DIM};
    const __half* passB[NPASS] = {g_phi + (size_t)bcol * D_DIM,
                                  g_plo + (size_t)bcol * D_DIM,
                                  g_phi + (size_t)bcol * D_DIM};

    // ldmatrix per-thread addressing (XOR-swizzled 128B rows).
    const int a_row  = wm * 64 + (lane & 15);
    const uint32_t a_base = (uint32_t)(a_row * 128);
    const uint32_t a_xor  = (uint32_t)((a_row & 7) << 4);
    const uint32_t a_sel  = (lane & 16) ? 16u : 0u;
    const int b_row  = wn * 64 + (lane & 7) + ((lane & 16) ? 8 : 0);
    const uint32_t b_base = (uint32_t)(BM * 128 + b_row * 128);
    const uint32_t b_xor  = (uint32_t)((b_row & 7) << 4);
    const uint32_t b_sel  = (lane & 8) ? 16u : 0u;

    float acc[4][8][4];
    #pragma unroll
    for (int i = 0; i < 4; i++)
        #pragma unroll
        for (int j = 0; j < 8; j++)
            #pragma unroll
            for (int k = 0; k < 4; k++) acc[i][j][k] = 0.0f;

    #pragma unroll
    for (int t = 0; t < STAGES - 1; t++) {
        load_tile(t, smem0, passA, passB, ls);
        CP_COMMIT();
    }

    for (int t = 0; t < TOT_TILES; t++) {
        CP_WAIT(STAGES - 2);
        __syncthreads();
        if (t + STAGES - 1 < TOT_TILES)
            load_tile(t + STAGES - 1, smem0, passA, passB, ls);
        CP_COMMIT();

        const uint32_t sbase = smem0 + (t % STAGES) * STAGE_BYTES;
        #pragma unroll
        for (int ks = 0; ks < BK / 16; ks++) {
            uint32_t af[4][4], bf[4][4];
            #pragma unroll
            for (int mi = 0; mi < 4; mi++)
                ldsm_x4(af[mi], sbase + a_base + mi * 16 * 128 +
                                ((ks * 32 + a_sel) ^ a_xor));
            #pragma unroll
            for (int ni = 0; ni < 4; ni++)
                ldsm_x4(bf[ni], sbase + b_base + ni * 16 * 128 +
                                ((ks * 32 + b_sel) ^ b_xor));
            #pragma unroll
            for (int mi = 0; mi < 4; mi++)
                #pragma unroll
                for (int nj = 0; nj < 8; nj++)
                    mma16816(acc[mi][nj], af[mi], &bf[nj >> 1][(nj & 1) * 2]);
        }
    }

    // Epilogue: store raw qp (softmax pass applies 2*qp - p2).
    #pragma unroll
    for (int mi = 0; mi < 4; mi++) {
        #pragma unroll
        for (int nj = 0; nj < 8; nj++) {
            const int r = brow + wm * 64 + mi * 16 + (lane >> 2);
            const int c = bcol + wn * 64 + nj * 8 + (lane & 3) * 2;
            float* o0 = out + (size_t)r * M_DIM + c;
            float* o1 = out + (size_t)(r + 8) * M_DIM + c;
            *reinterpret_cast<float2*>(o0) = make_float2(acc[mi][nj][0], acc[mi][nj][1]);
            *reinterpret_cast<float2*>(o1) = make_float2(acc[mi][nj][2], acc[mi][nj][3]);
        }
    }
}

// ---------------------------------------------------------------------------
// Kernel C: in-place row softmax of s[m] = 2*qp[n,m] - p2[m]. Warp per row.
// Online max/sum; second __ldcg pass (L2-hot) recomputes exp for the write.
// ---------------------------------------------------------------------------
__global__ __launch_bounds__(256) void softmax_kernel(float* __restrict__ out) {
    const int warp = threadIdx.x >> 5, lane = threadIdx.x & 31;
    const int row  = blockIdx.x * 8 + warp;
    float4* p = reinterpret_cast<float4*>(out + (size_t)row * M_DIM);
    const float4* pp = reinterpret_cast<const float4*>(g_p2);

    float m = -3.4e38f, sum = 0.0f;
    #pragma unroll
    for (int j = 0; j < 8; j++) {
        float4 v = __ldcg(&p[lane + 32 * j]);
        float4 q = pp[lane + 32 * j];
        float s0 = 2.0f * v.x - q.x, s1 = 2.0f * v.y - q.y;
        float s2 = 2.0f * v.z - q.z, s3 = 2.0f * v.w - q.w;
        float m4 = fmaxf(fmaxf(s0, s1), fmaxf(s2, s3));
        float mn = fmaxf(m, m4);
        sum = sum * __expf(m - mn)
            + __expf(s0 - mn) + __expf(s1 - mn)
            + __expf(s2 - mn) + __expf(s3 - mn);
        m = mn;
    }
    #pragma unroll
    for (int o = 16; o; o >>= 1) {
        float mo = __shfl_xor_sync(0xffffffffu, m, o);
        float so = __shfl_xor_sync(0xffffffffu, sum, o);
        float mn = fmaxf(m, mo);
        sum = sum * __expf(m - mn) + so * __expf(mo - mn);
        m = mn;
    }
    const float inv = 1.0f / sum;

    #pragma unroll
    for (int j = 0; j < 8; j++) {
        float4 v = __ldcg(&p[lane + 32 * j]);
        float4 q = pp[lane + 32 * j];
        float4 r;
        r.x = __expf(2.0f * v.x - q.x - m) * inv;
        r.y = __expf(2.0f * v.y - q.y - m) * inv;
        r.z = __expf(2.0f * v.z - q.z - m) * inv;
        r.w = __expf(2.0f * v.w - q.w - m) * inv;
        p[lane + 32 * j] = r;
    }
}

// ---------------------------------------------------------------------------
extern "C" void kernel_launch(void* const* d_in, const int* in_sizes, int n_in,
                              void* d_out, int out_size) {
    const float* query = (const float*)d_in[0];   // [N, 1024] fp32
    const float* proto = (const float*)d_in[1];   // [1024, 1024] fp32
    float* out = (float*)d_out;                   // [N, 1024] fp32
    const int N = in_sizes[0] / D_DIM;

    cudaFuncSetAttribute(gemm_kernel, cudaFuncAttributeMaxDynamicSharedMemorySize,
                         SMEM_DYN_BYTES);

    convert_kernel<<<(N + M_DIM) / 8, 256>>>(query, proto, N);

    dim3 grid(M_DIM / BN, N / BM);                // (4, 128) = 512 CTAs
    gemm_kernel<<<grid, 256, SMEM_DYN_BYTES>>>(out);

    softmax_kernel<<<N / 8, 256>>>(out);
}

// round 10
// speedup vs baseline: 1.1580x; 1.1580x over previous
#include <cuda_runtime.h>
#include <cuda_fp16.h>
#include <cstdint>

#define D_DIM 1024
#define M_DIM 1024
#define N_MAX 16384

#define BM 128
#define BN 128
#define BK 64                       // halves per k-tile = 128 bytes/row
#define STAGES 3
#define NPASS 3
#define TOT_TILES (NPASS * (D_DIM / BK))    // 48
#define HALF_TILES (TOT_TILES / 2)          // 24

#define STAGE_BYTES (BM * 128 + BN * 128)   // 32 KB (A then B)
#define SMEM_DYN_BYTES (STAGES * STAGE_BYTES)

// ---------------- static device scratch (no allocation allowed) -------------
__device__ __align__(16) float  g_p2[M_DIM];
__device__ __align__(16) __half g_qhi[(size_t)N_MAX * D_DIM];
__device__ __align__(16) __half g_qlo[(size_t)N_MAX * D_DIM];
__device__ __align__(16) __half g_phi[(size_t)M_DIM * D_DIM];
__device__ __align__(16) __half g_plo[(size_t)M_DIM * D_DIM];
// Partial sums for tail split-K tiles: worst case < 320 tiles of 128x128.
__device__ __align__(16) float  g_qpx[(size_t)320 * BM * BN];

// ---------------- helpers ----------------------------------------------------
__device__ __forceinline__ uint32_t smem_to_u32(const void* p) {
    uint32_t a;
    asm("{ .reg .u64 t; cvta.to.shared.u64 t, %1; cvt.u32.u64 %0, t; }" : "=r"(a) : "l"(p));
    return a;
}

__device__ __forceinline__ void cp_async16(uint32_t dst, const void* src) {
    asm volatile("cp.async.cg.shared.global [%0], [%1], 16;" :: "r"(dst), "l"(src) : "memory");
}
#define CP_COMMIT() asm volatile("cp.async.commit_group;" ::: "memory")
#define CP_WAIT(n)  asm volatile("cp.async.wait_group %0;" :: "n"(n) : "memory")

__device__ __forceinline__ void ldsm_x4(uint32_t* r, uint32_t addr) {
    asm volatile("ldmatrix.sync.aligned.m8n8.x4.shared.b16 {%0,%1,%2,%3}, [%4];"
                 : "=r"(r[0]), "=r"(r[1]), "=r"(r[2]), "=r"(r[3]) : "r"(addr));
}

__device__ __forceinline__ void mma16816(float* c, const uint32_t* a, const uint32_t* b) {
    asm volatile(
        "mma.sync.aligned.m16n8k16.row.col.f32.f16.f16.f32 "
        "{%0,%1,%2,%3}, {%4,%5,%6,%7}, {%8,%9}, {%0,%1,%2,%3};"
        : "+f"(c[0]), "+f"(c[1]), "+f"(c[2]), "+f"(c[3])
        : "r"(a[0]), "r"(a[1]), "r"(a[2]), "r"(a[3]), "r"(b[0]), "r"(b[1]));
}

// ---------------------------------------------------------------------------
// Kernel A: split fp32 -> (hi, lo) fp16 pairs for Q and P; fused p2 for P.
// ---------------------------------------------------------------------------
__global__ __launch_bounds__(256) void convert_kernel(const float* __restrict__ q,
                                                      const float* __restrict__ p, int nq) {
    const int row  = blockIdx.x * 8 + (threadIdx.x >> 5);
    const int lane = threadIdx.x & 31;
    const bool isQ = row < nq;
    const float* src = isQ ? (q + (size_t)row * D_DIM) : (p + (size_t)(row - nq) * D_DIM);
    __half* dhi = isQ ? (g_qhi + (size_t)row * D_DIM) : (g_phi + (size_t)(row - nq) * D_DIM);
    __half* dlo = isQ ? (g_qlo + (size_t)row * D_DIM) : (g_plo + (size_t)(row - nq) * D_DIM);

    float4 v[8];
    #pragma unroll
    for (int j = 0; j < 8; j++)
        v[j] = reinterpret_cast<const float4*>(src)[lane + 32 * j];

    #pragma unroll
    for (int j = 0; j < 8; j++) {
        __half h0 = __float2half_rn(v[j].x), h1 = __float2half_rn(v[j].y);
        __half h2 = __float2half_rn(v[j].z), h3 = __float2half_rn(v[j].w);
        __half l0 = __float2half_rn(v[j].x - __half2float(h0));
        __half l1 = __float2half_rn(v[j].y - __half2float(h1));
        __half l2 = __float2half_rn(v[j].z - __half2float(h2));
        __half l3 = __float2half_rn(v[j].w - __half2float(h3));
        __half2 hv[2] = {__halves2half2(h0, h1), __halves2half2(h2, h3)};
        __half2 lv[2] = {__halves2half2(l0, l1), __halves2half2(l2, l3)};
        reinterpret_cast<uint2*>(dhi)[lane + 32 * j] = *reinterpret_cast<uint2*>(hv);
        reinterpret_cast<uint2*>(dlo)[lane + 32 * j] = *reinterpret_cast<uint2*>(lv);
    }

    if (!isQ) {                                 // fused p2 (exact fp32)
        float s = 0.0f;
        #pragma unroll
        for (int j = 0; j < 8; j++)
            s += v[j].x * v[j].x + v[j].y * v[j].y + v[j].z * v[j].z + v[j].w * v[j].w;
        #pragma unroll
        for (int o = 16; o; o >>= 1) s += __shfl_xor_sync(0xffffffffu, s, o);
        if (lane == 0) g_p2[row - nq] = s;
    }
}

// ---------------------------------------------------------------------------
// Kernel B: HMMA GEMM (R8 proven config) + tail split-K.
// Tiles [0, normal): full 48 k-tiles -> out.
// Tiles [normal, normal+rem): two half-units each (k-tiles [0,24) -> out,
// k-tiles [24,48) -> g_qpx). Halves of the same tile are `rem` apart in bid.
// ---------------------------------------------------------------------------
struct LoadSlots { uint32_t dst[4]; int src[4]; };

__device__ __forceinline__ void load_tile(int kt, int stage, uint32_t smem0,
                                          const __half* const* passA,
                                          const __half* const* passB,
                                          const LoadSlots& ls) {
    const __half* A = passA[kt >> 4] + (kt & 15) * BK;
    const __half* B = passB[kt >> 4] + (kt & 15) * BK;
    const uint32_t sa = smem0 + stage * STAGE_BYTES;
    const uint32_t sb = sa + BM * 128;
    #pragma unroll
    for (int i = 0; i < 4; i++) cp_async16(sa + ls.dst[i], A + ls.src[i]);
    #pragma unroll
    for (int i = 0; i < 4; i++) cp_async16(sb + ls.dst[i], B + ls.src[i]);
}

__global__ __launch_bounds__(256, 2) void gemm_kernel(float* __restrict__ out,
                                                      int normal, int rem, int row_split) {
    extern __shared__ __align__(128) char dsm[];
    const int tid  = threadIdx.x;
    const int lane = tid & 31;
    const int wid  = tid >> 5;
    const int wm   = wid & 1;       // 2 warps along M
    const int wn   = wid >> 1;      // 4 warps along N

    int tile, kt0, nkt, half;
    if ((int)blockIdx.x < normal) {
        tile = blockIdx.x; kt0 = 0; nkt = TOT_TILES; half = 0;
    } else {
        const int u = blockIdx.x - normal;
        const int s = (u < rem) ? u : (u - rem);
        half = (u < rem) ? 0 : 1;
        tile = normal + s; kt0 = half * HALF_TILES; nkt = HALF_TILES;
    }
    const int brow = (tile >> 3) * BM;
    const int bcol = (tile & 7) * BN;

    const uint32_t smem0 = smem_to_u32(dsm);

    LoadSlots ls;
    #pragma unroll
    for (int i = 0; i < 4; i++) {
        int idx = i * 256 + tid, r = idx >> 3, c = idx & 7;
        uint32_t off = (uint32_t)(r * 128 + c * 16);
        ls.dst[i] = off ^ ((off >> 3) & 0x70);
        ls.src[i] = r * D_DIM + c * 8;
    }

    const __half* passA[NPASS] = {g_qhi + (size_t)brow * D_DIM,
                                  g_qhi + (size_t)brow * D_DIM,
                                  g_qlo + (size_t)brow * D_DIM};
    const __half* passB[NPASS] = {g_phi + (size_t)bcol * D_DIM,
                                  g_plo + (size_t)bcol * D_DIM,
                                  g_phi + (size_t)bcol * D_DIM};

    // ldmatrix per-thread addressing (XOR-swizzled 128B rows).
    const int a_row  = wm * 64 + (lane & 15);
    const uint32_t a_base = (uint32_t)(a_row * 128);
    const uint32_t a_xor  = (uint32_t)((a_row & 7) << 4);
    const uint32_t a_sel  = (lane & 16) ? 16u : 0u;
    const int b_row  = wn * 32 + (lane & 7) + ((lane & 16) ? 8 : 0);
    const uint32_t b_base = (uint32_t)(BM * 128 + b_row * 128);
    const uint32_t b_xor  = (uint32_t)((b_row & 7) << 4);
    const uint32_t b_sel  = (lane & 8) ? 16u : 0u;

    float acc[4][4][4];
    #pragma unroll
    for (int i = 0; i < 4; i++)
        #pragma unroll
        for (int j = 0; j < 4; j++)
            #pragma unroll
            for (int k = 0; k < 4; k++) acc[i][j][k] = 0.0f;

    load_tile(kt0, 0, smem0, passA, passB, ls); CP_COMMIT();
    load_tile(kt0 + 1, 1, smem0, passA, passB, ls); CP_COMMIT();

    for (int t = 0; t < nkt; t++) {
        CP_WAIT(STAGES - 2);
        __syncthreads();
        if (t + STAGES - 1 < nkt)
            load_tile(kt0 + t + STAGES - 1, (t + STAGES - 1) % STAGES,
                      smem0, passA, passB, ls);
        CP_COMMIT();

        const uint32_t sbase = smem0 + (t % STAGES) * STAGE_BYTES;
        #pragma unroll
        for (int ks = 0; ks < BK / 16; ks++) {
            uint32_t af[4][4], bf[2][4];
            #pragma unroll
            for (int mi = 0; mi < 4; mi++)
                ldsm_x4(af[mi], sbase + a_base + mi * 16 * 128 +
                                ((ks * 32 + a_sel) ^ a_xor));
            #pragma unroll
            for (int ni = 0; ni < 2; ni++)
                ldsm_x4(bf[ni], sbase + b_base + ni * 16 * 128 +
                                ((ks * 32 + b_sel) ^ b_xor));
            #pragma unroll
            for (int mi = 0; mi < 4; mi++)
                #pragma unroll
                for (int nj = 0; nj < 4; nj++)
                    mma16816(acc[mi][nj], af[mi], &bf[nj >> 1][(nj & 1) * 2]);
        }
    }

    // Epilogue: half 0 (and normal tiles) -> out; half 1 -> g_qpx.
    float* dst = half ? g_qpx : out;
    const int roff = half ? row_split : 0;
    #pragma unroll
    for (int mi = 0; mi < 4; mi++) {
        #pragma unroll
        for (int nj = 0; nj < 4; nj++) {
            const int r = brow + wm * 64 + mi * 16 + (lane >> 2);
            const int c = bcol + wn * 32 + nj * 8 + (lane & 3) * 2;
            float* o0 = dst + (size_t)(r - roff) * M_DIM + c;
            float* o1 = dst + (size_t)(r + 8 - roff) * M_DIM + c;
            *reinterpret_cast<float2*>(o0) = make_float2(acc[mi][nj][0], acc[mi][nj][1]);
            *reinterpret_cast<float2*>(o1) = make_float2(acc[mi][nj][2], acc[mi][nj][3]);
        }
    }
}

// ---------------------------------------------------------------------------
// Kernel C: row softmax of s[m] = 2*qp[n,m] - p2[m]; rows >= row_split add
// the split-K partial from g_qpx. Warp per row, online max/sum.
// ---------------------------------------------------------------------------
__global__ __launch_bounds__(256) void softmax_kernel(float* __restrict__ out, int row_split) {
    const int warp = threadIdx.x >> 5, lane = threadIdx.x & 31;
    const int row  = blockIdx.x * 8 + warp;
    float4* p = reinterpret_cast<float4*>(out + (size_t)row * M_DIM);
    const float4* pp = reinterpret_cast<const float4*>(g_p2);
    const bool ext = (row >= row_split);
    const float4* px = reinterpret_cast<const float4*>(
        g_qpx + (size_t)(ext ? (row - row_split) : 0) * M_DIM);

    float m = -3.4e38f, sum = 0.0f;
    #pragma unroll
    for (int j = 0; j < 8; j++) {
        float4 v = __ldcg(&p[lane + 32 * j]);
        if (ext) {
            float4 b = __ldcg(&px[lane + 32 * j]);
            v.x += b.x; v.y += b.y; v.z += b.z; v.w += b.w;
        }
        float4 q = pp[lane + 32 * j];
        float s0 = 2.0f * v.x - q.x, s1 = 2.0f * v.y - q.y;
        float s2 = 2.0f * v.z - q.z, s3 = 2.0f * v.w - q.w;
        float m4 = fmaxf(fmaxf(s0, s1), fmaxf(s2, s3));
        float mn = fmaxf(m, m4);
        sum = sum * __expf(m - mn)
            + __expf(s0 - mn) + __expf(s1 - mn)
            + __expf(s2 - mn) + __expf(s3 - mn);
        m = mn;
    }
    #pragma unroll
    for (int o = 16; o; o >>= 1) {
        float mo = __shfl_xor_sync(0xffffffffu, m, o);
        float so = __shfl_xor_sync(0xffffffffu, sum, o);
        float mn = fmaxf(m, mo);
        sum = sum * __expf(m - mn) + so * __expf(mo - mn);
        m = mn;
    }
    const float inv = 1.0f / sum;

    #pragma unroll
    for (int j = 0; j < 8; j++) {
        float4 v = __ldcg(&p[lane + 32 * j]);
        if (ext) {
            float4 b = __ldcg(&px[lane + 32 * j]);
            v.x += b.x; v.y += b.y; v.z += b.z; v.w += b.w;
        }
        float4 q = pp[lane + 32 * j];
        float4 r;
        r.x = __expf(2.0f * v.x - q.x - m) * inv;
        r.y = __expf(2.0f * v.y - q.y - m) * inv;
        r.z = __expf(2.0f * v.z - q.z - m) * inv;
        r.w = __expf(2.0f * v.w - q.w - m) * inv;
        p[lane + 32 * j] = r;
    }
}

// ---------------------------------------------------------------------------
extern "C" void kernel_launch(void* const* d_in, const int* in_sizes, int n_in,
                              void* d_out, int out_size) {
    const float* query = (const float*)d_in[0];   // [N, 1024] fp32
    const float* proto = (const float*)d_in[1];   // [1024, 1024] fp32
    float* out = (float*)d_out;                   // [N, 1024] fp32
    const int N = in_sizes[0] / D_DIM;

    cudaFuncSetAttribute(gemm_kernel, cudaFuncAttributeMaxDynamicSharedMemorySize,
                         SMEM_DYN_BYTES);

    int sm_count = 148;
    cudaDeviceGetAttribute(&sm_count, cudaDevAttrMultiProcessorCount, 0);
    const int slots   = 2 * sm_count;               // 2 CTA/SM residency
    const int n_tiles = (N / BM) * (M_DIM / BN);    // 1024
    int full_waves = n_tiles / slots;               // 3
    int rem = n_tiles - full_waves * slots;         // 136 (148 SM) / 112 (152 SM)
    rem -= rem % 8;                                 // keep row_split row-block aligned
    if (rem > 320) rem = 320;                       // g_qpx capacity guard
    const int normal   = n_tiles - rem;
    const int row_split = (normal / 8) * BM;        // rows >= this have a partial

    convert_kernel<<<(N + M_DIM) / 8, 256>>>(query, proto, N);

    gemm_kernel<<<normal + 2 * rem, 256, SMEM_DYN_BYTES>>>(out, normal, rem, row_split);

    softmax_kernel<<<N / 8, 256>>>(out, row_split);
}

// round 11
// speedup vs baseline: 1.1902x; 1.0278x over previous
#include <cuda_runtime.h>
#include <cuda_fp16.h>
#include <cstdint>

#define D_DIM 1024
#define M_DIM 1024
#define N_MAX 16384

#define BM 128
#define BN 128
#define BK 64                       // halves per k-tile = 128 bytes/row
#define STAGES 3
#define NPASS 3
#define TOT_TILES (NPASS * (D_DIM / BK))    // 48

#define STAGE_BYTES (BM * 128 + BN * 128)   // 32 KB (A then B)
#define SMEM_DYN_BYTES (STAGES * STAGE_BYTES)

// ---------------- static device scratch (no allocation allowed) -------------
__device__ __align__(16) float  g_p2[M_DIM];
__device__ __align__(16) __half g_qhi[(size_t)N_MAX * D_DIM];
__device__ __align__(16) __half g_qlo[(size_t)N_MAX * D_DIM];
__device__ __align__(16) __half g_phi[(size_t)M_DIM * D_DIM];
__device__ __align__(16) __half g_plo[(size_t)M_DIM * D_DIM];

// ---------------- helpers ----------------------------------------------------
__device__ __forceinline__ uint32_t smem_to_u32(const void* p) {
    uint32_t a;
    asm("{ .reg .u64 t; cvta.to.shared.u64 t, %1; cvt.u32.u64 %0, t; }" : "=r"(a) : "l"(p));
    return a;
}

__device__ __forceinline__ void cp_async16(uint32_t dst, const void* src) {
    asm volatile("cp.async.cg.shared.global [%0], [%1], 16;" :: "r"(dst), "l"(src) : "memory");
}
#define CP_COMMIT() asm volatile("cp.async.commit_group;" ::: "memory")
#define CP_WAIT(n)  asm volatile("cp.async.wait_group %0;" :: "n"(n) : "memory")

__device__ __forceinline__ void ldsm_x4(uint32_t* r, uint32_t addr) {
    asm volatile("ldmatrix.sync.aligned.m8n8.x4.shared.b16 {%0,%1,%2,%3}, [%4];"
                 : "=r"(r[0]), "=r"(r[1]), "=r"(r[2]), "=r"(r[3]) : "r"(addr));
}

__device__ __forceinline__ void mma16816(float* c, const uint32_t* a, const uint32_t* b) {
    asm volatile(
        "mma.sync.aligned.m16n8k16.row.col.f32.f16.f16.f32 "
        "{%0,%1,%2,%3}, {%4,%5,%6,%7}, {%8,%9}, {%0,%1,%2,%3};"
        : "+f"(c[0]), "+f"(c[1]), "+f"(c[2]), "+f"(c[3])
        : "r"(a[0]), "r"(a[1]), "r"(a[2]), "r"(a[3]), "r"(b[0]), "r"(b[1]));
}

// ---------------------------------------------------------------------------
// Kernel A: split fp32 -> (hi, lo) fp16 pairs for Q and P; fused p2 for P.
// Warp per row; each thread owns 8 consecutive floats per group -> 16B stores.
// Streaming loads/stores bypass L1 (consumed via cp.async / next kernel only).
// ---------------------------------------------------------------------------
__global__ __launch_bounds__(256) void convert_kernel(const float* __restrict__ q,
                                                      const float* __restrict__ p, int nq) {
    const int row  = blockIdx.x * 8 + (threadIdx.x >> 5);
    const int lane = threadIdx.x & 31;
    const bool isQ = row < nq;
    const float* src = isQ ? (q + (size_t)row * D_DIM) : (p + (size_t)(row - nq) * D_DIM);
    __half* dhi = isQ ? (g_qhi + (size_t)row * D_DIM) : (g_phi + (size_t)(row - nq) * D_DIM);
    __half* dlo = isQ ? (g_qlo + (size_t)row * D_DIM) : (g_plo + (size_t)(row - nq) * D_DIM);

    // 4 groups x 8 consecutive floats per thread (2 float4 loads each).
    float4 v[8];
    #pragma unroll
    for (int g = 0; g < 4; g++) {
        const int idx = g * 256 + lane * 8;
        v[2 * g + 0] = __ldcg(reinterpret_cast<const float4*>(src + idx));
        v[2 * g + 1] = __ldcg(reinterpret_cast<const float4*>(src + idx + 4));
    }

    #pragma unroll
    for (int g = 0; g < 4; g++) {
        const int idx = g * 256 + lane * 8;
        const float* f = reinterpret_cast<const float*>(&v[2 * g]);
        __half h[8], l[8];
        #pragma unroll
        for (int e = 0; e < 8; e++) {
            h[e] = __float2half_rn(f[e]);
            l[e] = __float2half_rn(f[e] - __half2float(h[e]));
        }
        __stcg(reinterpret_cast<uint4*>(dhi + idx), *reinterpret_cast<const uint4*>(h));
        __stcg(reinterpret_cast<uint4*>(dlo + idx), *reinterpret_cast<const uint4*>(l));
    }

    if (!isQ) {                                 // fused p2 (exact fp32)
        float s = 0.0f;
        #pragma unroll
        for (int j = 0; j < 8; j++)
            s += v[j].x * v[j].x + v[j].y * v[j].y + v[j].z * v[j].z + v[j].w * v[j].w;
        #pragma unroll
        for (int o = 16; o; o >>= 1) s += __shfl_xor_sync(0xffffffffu, s, o);
        if (lane == 0) g_p2[row - nq] = s;
    }
}

// ---------------------------------------------------------------------------
// Kernel B: HMMA GEMM (R8 proven config — pipe-balanced, do not perturb).
// qp = Qhi*Phi^T + Qhi*Plo^T + Qlo*Phi^T -> out
// 128x128 CTA tile, BK=64, 3-stage cp.async pipeline, one barrier per k-tile.
// ---------------------------------------------------------------------------
struct LoadSlots { uint32_t dst[4]; int src[4]; };

__device__ __forceinline__ void load_tile(int t, uint32_t smem0,
                                          const __half* const* passA,
                                          const __half* const* passB,
                                          const LoadSlots& ls) {
    const int stage = t % STAGES;
    const __half* A = passA[t >> 4] + (t & 15) * BK;
    const __half* B = passB[t >> 4] + (t & 15) * BK;
    const uint32_t sa = smem0 + stage * STAGE_BYTES;
    const uint32_t sb = sa + BM * 128;
    #pragma unroll
    for (int i = 0; i < 4; i++) cp_async16(sa + ls.dst[i], A + ls.src[i]);
    #pragma unroll
    for (int i = 0; i < 4; i++) cp_async16(sb + ls.dst[i], B + ls.src[i]);
}

__global__ __launch_bounds__(256, 2) void gemm_kernel(float* __restrict__ out) {
    extern __shared__ __align__(128) char dsm[];
    const int tid  = threadIdx.x;
    const int lane = tid & 31;
    const int wid  = tid >> 5;
    const int wm   = wid & 1;       // 2 warps along M
    const int wn   = wid >> 1;      // 4 warps along N
    const int brow = blockIdx.y * BM;
    const int bcol = blockIdx.x * BN;

    const uint32_t smem0 = smem_to_u32(dsm);

    LoadSlots ls;
    #pragma unroll
    for (int i = 0; i < 4; i++) {
        int idx = i * 256 + tid, r = idx >> 3, c = idx & 7;
        uint32_t off = (uint32_t)(r * 128 + c * 16);
        ls.dst[i] = off ^ ((off >> 3) & 0x70);
        ls.src[i] = r * D_DIM + c * 8;
    }

    const __half* passA[NPASS] = {g_qhi + (size_t)brow * D_DIM,
                                  g_qhi + (size_t)brow * D_DIM,
                                  g_qlo + (size_t)brow * D_DIM};
    const __half* passB[NPASS] = {g_phi + (size_t)bcol * D_DIM,
                                  g_plo + (size_t)bcol * D_DIM,
                                  g_phi + (size_t)bcol * D_DIM};

    // ldmatrix per-thread addressing (XOR-swizzled 128B rows).
    const int a_row  = wm * 64 + (lane & 15);
    const uint32_t a_base = (uint32_t)(a_row * 128);
    const uint32_t a_xor  = (uint32_t)((a_row & 7) << 4);
    const uint32_t a_sel  = (lane & 16) ? 16u : 0u;
    const int b_row  = wn * 32 + (lane & 7) + ((lane & 16) ? 8 : 0);
    const uint32_t b_base = (uint32_t)(BM * 128 + b_row * 128);
    const uint32_t b_xor  = (uint32_t)((b_row & 7) << 4);
    const uint32_t b_sel  = (lane & 8) ? 16u : 0u;

    float acc[4][4][4];
    #pragma unroll
    for (int i = 0; i < 4; i++)
        #pragma unroll
        for (int j = 0; j < 4; j++)
            #pragma unroll
            for (int k = 0; k < 4; k++) acc[i][j][k] = 0.0f;

    #pragma unroll
    for (int t = 0; t < STAGES - 1; t++) {
        load_tile(t, smem0, passA, passB, ls);
        CP_COMMIT();
    }

    for (int t = 0; t < TOT_TILES; t++) {
        CP_WAIT(STAGES - 2);
        __syncthreads();
        if (t + STAGES - 1 < TOT_TILES)
            load_tile(t + STAGES - 1, smem0, passA, passB, ls);
        CP_COMMIT();

        const uint32_t sbase = smem0 + (t % STAGES) * STAGE_BYTES;
        #pragma unroll
        for (int ks = 0; ks < BK / 16; ks++) {
            uint32_t af[4][4], bf[2][4];
            #pragma unroll
            for (int mi = 0; mi < 4; mi++)
                ldsm_x4(af[mi], sbase + a_base + mi * 16 * 128 +
                                ((ks * 32 + a_sel) ^ a_xor));
            #pragma unroll
            for (int ni = 0; ni < 2; ni++)
                ldsm_x4(bf[ni], sbase + b_base + ni * 16 * 128 +
                                ((ks * 32 + b_sel) ^ b_xor));
            #pragma unroll
            for (int mi = 0; mi < 4; mi++)
                #pragma unroll
                for (int nj = 0; nj < 4; nj++)
                    mma16816(acc[mi][nj], af[mi], &bf[nj >> 1][(nj & 1) * 2]);
        }
    }

    // Epilogue: store raw qp (softmax pass applies 2*qp - p2).
    #pragma unroll
    for (int mi = 0; mi < 4; mi++) {
        #pragma unroll
        for (int nj = 0; nj < 4; nj++) {
            const int r = brow + wm * 64 + mi * 16 + (lane >> 2);
            const int c = bcol + wn * 32 + nj * 8 + (lane & 3) * 2;
            float* o0 = out + (size_t)r * M_DIM + c;
            float* o1 = out + (size_t)(r + 8) * M_DIM + c;
            *reinterpret_cast<float2*>(o0) = make_float2(acc[mi][nj][0], acc[mi][nj][1]);
            *reinterpret_cast<float2*>(o1) = make_float2(acc[mi][nj][2], acc[mi][nj][3]);
        }
    }
}

// ---------------------------------------------------------------------------
// Kernel C: in-place row softmax of s[m] = 2*qp[n,m] - p2[m]. Warp per row.
// Hybrid: first half of row cached in regs (s[16]); second half recomputed
// from an L2-hot reload in pass 2. Online max/sum across both halves.
// ---------------------------------------------------------------------------
__global__ __launch_bounds__(256) void softmax_kernel(float* __restrict__ out) {
    const int warp = threadIdx.x >> 5, lane = threadIdx.x & 31;
    const int row  = blockIdx.x * 8 + warp;
    float4* p = reinterpret_cast<float4*>(out + (size_t)row * M_DIM);
    const float4* pp = reinterpret_cast<const float4*>(g_p2);

    float sc[16];                   // cached logits for j = 0..3
    float m = -3.4e38f, sum = 0.0f;
    #pragma unroll
    for (int j = 0; j < 8; j++) {
        float4 v = __ldcg(&p[lane + 32 * j]);
        float4 q = pp[lane + 32 * j];
        float s0 = 2.0f * v.x - q.x, s1 = 2.0f * v.y - q.y;
        float s2 = 2.0f * v.z - q.z, s3 = 2.0f * v.w - q.w;
        if (j < 4) { sc[4*j] = s0; sc[4*j+1] = s1; sc[4*j+2] = s2; sc[4*j+3] = s3; }
        float m4 = fmaxf(fmaxf(s0, s1), fmaxf(s2, s3));
        float mn = fmaxf(m, m4);
        sum = sum * __expf(m - mn)
            + __expf(s0 - mn) + __expf(s1 - mn)
            + __expf(s2 - mn) + __expf(s3 - mn);
        m = mn;
    }
    #pragma unroll
    for (int o = 16; o; o >>= 1) {
        float mo = __shfl_xor_sync(0xffffffffu, m, o);
        float so = __shfl_xor_sync(0xffffffffu, sum, o);
        float mn = fmaxf(m, mo);
        sum = sum * __expf(m - mn) + so * __expf(mo - mn);
        m = mn;
    }
    const float inv = 1.0f / sum;

    #pragma unroll
    for (int j = 0; j < 4; j++) {                  // cached half
        float4 r;
        r.x = __expf(sc[4*j]   - m) * inv;
        r.y = __expf(sc[4*j+1] - m) * inv;
        r.z = __expf(sc[4*j+2] - m) * inv;
        r.w = __expf(sc[4*j+3] - m) * inv;
        p[lane + 32 * j] = r;
    }
    #pragma unroll
    for (int j = 4; j < 8; j++) {                  // recomputed half (L2-hot)
        float4 v = __ldcg(&p[lane + 32 * j]);
        float4 q = pp[lane + 32 * j];
        float4 r;
        r.x = __expf(2.0f * v.x - q.x - m) * inv;
        r.y = __expf(2.0f * v.y - q.y - m) * inv;
        r.z = __expf(2.0f * v.z - q.z - m) * inv;
        r.w = __expf(2.0f * v.w - q.w - m) * inv;
        p[lane + 32 * j] = r;
    }
}

// ---------------------------------------------------------------------------
extern "C" void kernel_launch(void* const* d_in, const int* in_sizes, int n_in,
                              void* d_out, int out_size) {
    const float* query = (const float*)d_in[0];   // [N, 1024] fp32
    const float* proto = (const float*)d_in[1];   // [1024, 1024] fp32
    float* out = (float*)d_out;                   // [N, 1024] fp32
    const int N = in_sizes[0] / D_DIM;

    cudaFuncSetAttribute(gemm_kernel, cudaFuncAttributeMaxDynamicSharedMemorySize,
                         SMEM_DYN_BYTES);

    convert_kernel<<<(N + M_DIM) / 8, 256>>>(query, proto, N);

    dim3 grid(M_DIM / BN, N / BM);                // (8, 128)
    gemm_kernel<<<grid, 256, SMEM_DYN_BYTES>>>(out);

    softmax_kernel<<<N / 8, 256>>>(out);
}